// round 9
// baseline (speedup 1.0000x reference)
#include <cuda_runtime.h>

#define H 1024
#define B 8
#define T 4096

// Scratch: v[b][i] = sum_j W[i][j] * context[b][j]
__device__ float g_v[B * H];

// ───────────────────────── Kernel 1: v = W @ ctx ─────────────────────────
// 256 blocks x 256 threads, 4 W rows per block. TRIGGER FIRES FIRST:
// the dependent score grid may launch immediately and overlap its states
// DRAM loads with this kernel; its cudaGridDependencySynchronize() still
// waits for our completion before touching g_v.
__global__ void __launch_bounds__(256) compute_v_kernel(
    const float* __restrict__ W, const float* __restrict__ ctx)
{
    cudaTriggerProgrammaticLaunchCompletion();

    __shared__ float sctx[B * H];
    __shared__ float red[4][8][9];

    const int tid  = threadIdx.x;
    const int lane = tid & 31;
    const int warp = tid >> 5;

#pragma unroll
    for (int k = 0; k < 8; k++)
        reinterpret_cast<float4*>(sctx)[tid + 256 * k] =
            reinterpret_cast<const float4*>(ctx)[tid + 256 * k];

    float4 w[4];
#pragma unroll
    for (int r = 0; r < 4; r++)
        w[r] = reinterpret_cast<const float4*>(W + (size_t)(blockIdx.x * 4 + r) * H)[tid];

    __syncthreads();

#pragma unroll
    for (int r = 0; r < 4; r++) {
        float acc[B];
#pragma unroll
        for (int b = 0; b < B; b++) {
            const float4 c = reinterpret_cast<const float4*>(sctx + b * H)[tid];
            acc[b] = w[r].x * c.x + w[r].y * c.y + w[r].z * c.z + w[r].w * c.w;
        }
#pragma unroll
        for (int b = 0; b < B; b++) {
#pragma unroll
            for (int o = 16; o; o >>= 1)
                acc[b] += __shfl_xor_sync(0xFFFFFFFFu, acc[b], o);
        }
        if (lane == 0) {
#pragma unroll
            for (int b = 0; b < B; b++) red[r][warp][b] = acc[b];
        }
    }
    __syncthreads();

    if (tid < 4 * B) {
        const int r = tid >> 3, b = tid & 7;
        float s = 0.0f;
#pragma unroll
        for (int wi = 0; wi < 8; wi++) s += red[r][wi][b];
        g_v[b * H + blockIdx.x * 4 + r] = s;
    }
}

// ───────────────────────── Kernel 2: scores ─────────────────────────
// Measured-best engine: one (b,t) row per warp, 512-thread blocks
// (16 rows/block), 2048 blocks, no smem/sync. 8 front-batched LDG.128
// per warp issued BEFORE the PDL dependency sync. v via __ldg (L1/L2-hot).
__global__ void __launch_bounds__(512) score_kernel(
    const float* __restrict__ states,  // (B, T, H)
    const float* __restrict__ bias,    // (1,)
    float* __restrict__ out)           // (B*T,)
{
    const int lane = threadIdx.x & 31;
    const int row  = blockIdx.x * 16 + (threadIdx.x >> 5);
    const int b    = row >> 12;        // row / T

    const float4* s4 = reinterpret_cast<const float4*>(states + (size_t)row * H);

    // Front-batch the 8 DRAM loads (one full 4 KB row per warp).
    float4 x[8];
#pragma unroll
    for (int k = 0; k < 8; k++) x[k] = s4[lane + 32 * k];

    const float bb = bias[0];   // input, not produced by compute_v

    // Wait for compute_v's g_v (overlapped with the loads above).
    cudaGridDependencySynchronize();

    const float4* v4 = reinterpret_cast<const float4*>(g_v + b * H);
    float acc0 = 0.0f, acc1 = 0.0f;
#pragma unroll
    for (int k = 0; k < 8; k += 2) {
        const float4 w0 = __ldg(v4 + lane + 32 * k);
        const float4 w1 = __ldg(v4 + lane + 32 * (k + 1));
        acc0 += x[k].x * w0.x + x[k].y * w0.y + x[k].z * w0.z + x[k].w * w0.w;
        acc1 += x[k+1].x * w1.x + x[k+1].y * w1.y + x[k+1].z * w1.z + x[k+1].w * w1.w;
    }
    float acc = acc0 + acc1;

#pragma unroll
    for (int o = 16; o; o >>= 1)
        acc += __shfl_xor_sync(0xFFFFFFFFu, acc, o);

    if (lane == 0) out[row] = acc + bb;
}

extern "C" void kernel_launch(void* const* d_in, const int* in_sizes, int n_in,
                              void* d_out, int out_size)
{
    const float* states = (const float*)d_in[0];   // (B, T, H)
    const float* ctx    = (const float*)d_in[1];   // (B, H)
    const float* W      = (const float*)d_in[2];   // (1, H, H)
    const float* bias   = (const float*)d_in[3];   // (1,)

    compute_v_kernel<<<H / 4, 256>>>(W, ctx);

    cudaLaunchConfig_t cfg = {};
    cfg.gridDim  = dim3((B * T) / 16);
    cfg.blockDim = dim3(512);
    cfg.dynamicSmemBytes = 0;
    cfg.stream = 0;
    cudaLaunchAttribute attr[1];
    attr[0].id = cudaLaunchAttributeProgrammaticStreamSerialization;
    attr[0].val.programmaticStreamSerializationAllowed = 1;
    cfg.attrs = attr;
    cfg.numAttrs = 1;
    cudaLaunchKernelEx(&cfg, score_kernel, states, bias, (float*)d_out);
}

// round 10
// speedup vs baseline: 1.0703x; 1.0703x over previous
#include <cuda_runtime.h>

#define H 1024
#define B 8
#define T 4096
#define NROWS (B * T)

#define SCORE_GRID 296                    // 148 SMs x 2 blocks
#define NWARPS (SCORE_GRID * 8)           // 2368 warps, ~14 rows each

__device__ float g_v[B * H];

// ───────────────────────── Kernel 1: v = W @ ctx ─────────────────────────
// 256 blocks x 256 threads, 4 W rows per block; ctx staged in smem once.
// Trigger at END (the R7-measured-good PDL config for persistent consumers).
__global__ void __launch_bounds__(256) compute_v_kernel(
    const float* __restrict__ W, const float* __restrict__ ctx)
{
    __shared__ float sctx[B * H];
    __shared__ float red[4][8][9];

    const int tid  = threadIdx.x;
    const int lane = tid & 31;
    const int warp = tid >> 5;

#pragma unroll
    for (int k = 0; k < 8; k++)
        reinterpret_cast<float4*>(sctx)[tid + 256 * k] =
            reinterpret_cast<const float4*>(ctx)[tid + 256 * k];

    float4 w[4];
#pragma unroll
    for (int r = 0; r < 4; r++)
        w[r] = reinterpret_cast<const float4*>(W + (size_t)(blockIdx.x * 4 + r) * H)[tid];

    __syncthreads();

#pragma unroll
    for (int r = 0; r < 4; r++) {
        float acc[B];
#pragma unroll
        for (int b = 0; b < B; b++) {
            const float4 c = reinterpret_cast<const float4*>(sctx + b * H)[tid];
            acc[b] = w[r].x * c.x + w[r].y * c.y + w[r].z * c.z + w[r].w * c.w;
        }
#pragma unroll
        for (int b = 0; b < B; b++) {
#pragma unroll
            for (int o = 16; o; o >>= 1)
                acc[b] += __shfl_xor_sync(0xFFFFFFFFu, acc[b], o);
        }
        if (lane == 0) {
#pragma unroll
            for (int b = 0; b < B; b++) red[r][warp][b] = acc[b];
        }
    }
    __syncthreads();

    if (tid < 4 * B) {
        const int r = tid >> 3, b = tid & 7;
        float s = 0.0f;
#pragma unroll
        for (int wi = 0; wi < 8; wi++) s += red[r][wi][b];
        g_v[b * H + blockIdx.x * 4 + r] = s;
    }
    cudaTriggerProgrammaticLaunchCompletion();
}

// ───────────────────────── Kernel 2: scores ─────────────────────────
__device__ __forceinline__ void load_row(float4 (&x)[8],
                                         const float* __restrict__ states,
                                         int row, int lane)
{
    const float4* s4 = reinterpret_cast<const float4*>(states + (size_t)row * H);
#pragma unroll
    for (int k = 0; k < 8; k++) x[k] = s4[lane + 32 * k];
}

__device__ __forceinline__ void dot_store(const float4 (&x)[8],
                                          int row, int lane, float bb,
                                          float* __restrict__ out)
{
    const float4* v4 = reinterpret_cast<const float4*>(g_v + ((row >> 12) << 10));
    float acc0 = 0.0f, acc1 = 0.0f;
#pragma unroll
    for (int k = 0; k < 8; k += 2) {
        const float4 w0 = __ldg(v4 + lane + 32 * k);
        const float4 w1 = __ldg(v4 + lane + 32 * (k + 1));
        acc0 += x[k].x * w0.x + x[k].y * w0.y + x[k].z * w0.z + x[k].w * w0.w;
        acc1 += x[k+1].x * w1.x + x[k+1].y * w1.y + x[k+1].z * w1.z + x[k+1].w * w1.w;
    }
    float acc = acc0 + acc1;
#pragma unroll
    for (int o = 16; o; o >>= 1)
        acc += __shfl_xor_sync(0xFFFFFFFFu, acc, o);
    if (lane == 0) out[row] = acc + bb;
}

// Persistent: 296 blocks x 256 threads, one warp strides rows by NWARPS.
// Register ping-pong (xa/xb statically named): row i+1's 8 LDG.128 are in
// flight while row i's dot/reduce/store runs -> ~100% load duty cycle,
// no wave-transition tail, no smem, no __syncthreads in the loop.
__global__ void __launch_bounds__(256, 2) score_kernel(
    const float* __restrict__ states,  // (B, T, H)
    const float* __restrict__ bias,    // (1,)
    float* __restrict__ out)           // (B*T,)
{
    const int lane = threadIdx.x & 31;
    const int wg   = blockIdx.x * 8 + (threadIdx.x >> 5);

    float4 xa[8], xb[8];

    int ra = wg;                       // first row for buffer A
    load_row(xa, states, ra, lane);    // issued BEFORE the dependency sync
    const float bb = bias[0];

    cudaGridDependencySynchronize();   // g_v valid; loads above overlapped

    int rb = ra + NWARPS;
    for (;;) {
        if (rb < NROWS) load_row(xb, states, rb, lane);   // prefetch next
        dot_store(xa, ra, lane, bb, out);                 // consume current
        if (rb >= NROWS) break;

        ra = rb + NWARPS;
        if (ra < NROWS) load_row(xa, states, ra, lane);
        dot_store(xb, rb, lane, bb, out);
        if (ra >= NROWS) break;

        rb = ra + NWARPS;
    }
}

extern "C" void kernel_launch(void* const* d_in, const int* in_sizes, int n_in,
                              void* d_out, int out_size)
{
    const float* states = (const float*)d_in[0];   // (B, T, H)
    const float* ctx    = (const float*)d_in[1];   // (B, H)
    const float* W      = (const float*)d_in[2];   // (1, H, H)
    const float* bias   = (const float*)d_in[3];   // (1,)

    compute_v_kernel<<<H / 4, 256>>>(W, ctx);

    cudaLaunchConfig_t cfg = {};
    cfg.gridDim  = dim3(SCORE_GRID);
    cfg.blockDim = dim3(256);
    cfg.dynamicSmemBytes = 0;
    cfg.stream = 0;
    cudaLaunchAttribute attr[1];
    attr[0].id = cudaLaunchAttributeProgrammaticStreamSerialization;
    attr[0].val.programmaticStreamSerializationAllowed = 1;
    cfg.attrs = attr;
    cfg.numAttrs = 1;
    cudaLaunchKernelEx(&cfg, score_kernel, states, bias, (float*)d_out);
}